// round 7
// baseline (speedup 1.0000x reference)
#include <cuda_runtime.h>
#include <cstdint>
#include <cstdio>

// Problem constants
#define B_     8
#define DSEM   256
#define DTOT   292
#define T_     2048
#define NROW   16384          // B*T
#define NCODE  8192
#define ZSTRIDE (DTOT * T_)   // 598016
#define NAC    (8 * 36 * 2048)  // 589824

// smem pitches
#define ZP 258                // z tile row pitch (floats), 128 rows x 256 k
#define CP 18                 // codebook tile pitch (floats), 128 codes x 16 k

// scratch (no cudaMalloc allowed)
__device__ float g_znorm[NROW];
__device__ float g_cnorm[NCODE];
__device__ float g_loss;
__device__ float g_dummy[NAC];   // sink for missing output regions

// ---------------------------------------------------------------------------
// Prep: row norms of z_sem, codebook norms, zero loss accumulator
// ---------------------------------------------------------------------------
__global__ void prep_kernel(const float* __restrict__ z, const float* __restrict__ cb)
{
    int tid = blockIdx.x * blockDim.x + threadIdx.x;
    if (tid == 0) g_loss = 0.0f;
    if (tid < NROW) {
        int b = tid >> 11, t = tid & 2047;
        const float* p = z + (size_t)b * ZSTRIDE + t;
        float s = 0.0f;
        #pragma unroll 8
        for (int d = 0; d < DSEM; d++) { float v = p[(size_t)d * T_]; s += v * v; }
        g_znorm[tid] = s;
    }
    if (tid < NCODE) {
        const float* p = cb + (size_t)tid * DSEM;
        float s = 0.0f;
        #pragma unroll 8
        for (int d = 0; d < DSEM; d++) { float v = p[d]; s += v * v; }
        g_cnorm[tid] = s;
    }
}

// packed fp32x2 FMA (SASS FFMA2) — only reachable via PTX
#define FMA2(acc, a, b) \
    asm("fma.rn.f32x2 %0, %1, %2, %0;" : "+l"(acc) : "l"(a), "l"(b))

// ---------------------------------------------------------------------------
// Fused GEMM + argmin + z_q gather + sem output + loss partial
// grid = 128 CTAs (128 rows each), 256 threads (16 tx codes x 16 ty rows)
// ---------------------------------------------------------------------------
__global__ __launch_bounds__(256, 1)
void vq_kernel(const float* __restrict__ z, const float* __restrict__ cb,
               float* __restrict__ outZ, float* __restrict__ outIdx)
{
    extern __shared__ float sm[];
    float* zsm = sm;                    // 128 * ZP floats (z tile, resident)
    float* csm = sm + 128 * ZP;         // 2 * 128 * CP floats (codebook, double buf)

    int tid = threadIdx.x;
    int tx = tid & 15, ty = tid >> 4;
    int n0 = blockIdx.x * 128;          // first row of this CTA
    int bb = n0 >> 11, t0 = n0 & 2047;
    const float* zb = z + (size_t)bb * ZSTRIDE + t0;

    // load z tile: zsm[r][k], coalesced along t (=r)
    for (int i = tid; i < 128 * DSEM; i += 256) {
        int d = i >> 7, r = i & 127;
        zsm[r * ZP + d] = zb[(size_t)d * T_ + r];
    }

    float zn[8], best[8];
    int   bidx[8];
    #pragma unroll
    for (int i = 0; i < 8; i++) {
        zn[i]   = g_znorm[n0 + ty + 16 * i];
        best[i] = 3.4e38f;
        bidx[i] = 0;
    }

    // codebook chunk loader: thread (c_ld, h_ld) loads 8 floats of one code row
    int c_ld = tid >> 1;
    int h_ld = (tid & 1) * 8;
    float4 p0, p1;
    {
        const float* g = cb + (size_t)c_ld * DSEM + h_ld;     // tile 0, chunk 0
        p0 = *(const float4*)g; p1 = *(const float4*)(g + 4);
    }
    __syncthreads();

    #pragma unroll 1
    for (int tile = 0; tile < 64; tile++) {
        int ct0 = tile * 128;
        unsigned long long acc[8][8];
        #pragma unroll
        for (int i = 0; i < 8; i++)
            #pragma unroll
            for (int j = 0; j < 8; j++) acc[i][j] = 0ULL;

        #pragma unroll 1
        for (int kc16 = 0; kc16 < 16; kc16++) {
            int bufo = (kc16 & 1) * (128 * CP);
            // store prefetched chunk (hazard covered by the mid-barrier chain)
            float* cd = csm + bufo + c_ld * CP + h_ld;
            ((float2*)cd)[0] = make_float2(p0.x, p0.y);
            ((float2*)cd)[1] = make_float2(p0.z, p0.w);
            ((float2*)cd)[2] = make_float2(p1.x, p1.y);
            ((float2*)cd)[3] = make_float2(p1.z, p1.w);
            // prefetch next chunk into registers
            {
                int nt = tile, nk = kc16 + 1;
                if (nk == 16) { nk = 0; nt = tile + 1; }
                if (nt < 64) {
                    const float* g = cb + (size_t)(nt * 128 + c_ld) * DSEM + nk * 16 + h_ld;
                    p0 = *(const float4*)g; p1 = *(const float4*)(g + 4);
                }
            }
            __syncthreads();

            int kc = kc16 * 16;
            #pragma unroll
            for (int kp = 0; kp < 8; kp++) {
                unsigned long long av[8], bv[8];
                #pragma unroll
                for (int i = 0; i < 8; i++)
                    av[i] = *(const unsigned long long*)&zsm[(ty + 16 * i) * ZP + kc + 2 * kp];
                #pragma unroll
                for (int j = 0; j < 8; j++)
                    bv[j] = *(const unsigned long long*)&csm[bufo + (tx + 16 * j) * CP + 2 * kp];
                #pragma unroll
                for (int i = 0; i < 8; i++)
                    #pragma unroll
                    for (int j = 0; j < 8; j++)
                        FMA2(acc[i][j], av[i], bv[j]);
            }
        }

        // tile epilogue: distances + running argmin (ascending order => first-min kept)
        float cn[8];
        #pragma unroll
        for (int j = 0; j < 8; j++) cn[j] = g_cnorm[ct0 + tx + 16 * j];
        #pragma unroll
        for (int i = 0; i < 8; i++) {
            #pragma unroll
            for (int j = 0; j < 8; j++) {
                unsigned long long v = acc[i][j];
                float lo = __uint_as_float((unsigned)v);
                float hi = __uint_as_float((unsigned)(v >> 32));
                float dot = lo + hi;
                float dist = (zn[i] - 2.0f * dot) + cn[j];   // replicate ref op order
                if (dist < best[i]) { best[i] = dist; bidx[i] = ct0 + tx + 16 * j; }
            }
        }
    }

    // reduce argmin across the 16 tx lanes (contiguous lanes per ty)
    #pragma unroll
    for (int i = 0; i < 8; i++) {
        #pragma unroll
        for (int s = 1; s < 16; s <<= 1) {
            float od = __shfl_xor_sync(0xffffffffu, best[i], s, 16);
            int   oi = __shfl_xor_sync(0xffffffffu, bidx[i], s, 16);
            if (od < best[i] || (od == best[i] && oi < bidx[i])) { best[i] = od; bidx[i] = oi; }
        }
    }

    int* sIdx = (int*)csm;              // reuse codebook smem
    __syncthreads();                    // all GEMM reads of csm done
    if (tx == 0) {
        #pragma unroll
        for (int i = 0; i < 8; i++) {
            int r = ty + 16 * i;
            sIdx[r] = bidx[i];
            outIdx[n0 + r] = (float)bidx[i];
        }
    }
    __syncthreads();

    // z_q gather + sem output (in-place into zsm) + loss partial
    float lacc = 0.0f;
    #pragma unroll 4
    for (int r = 0; r < 128; r++) {
        float cq = cb[(size_t)sIdx[r] * DSEM + tid];   // coalesced: all lanes same row
        float zv = zsm[r * ZP + tid];
        float df = cq - zv;
        float o  = zv + df;                            // z_sem + (z_q - z_sem), exact ref chain
        lacc = fmaf(df, df, lacc);
        zsm[r * ZP + tid] = o;
    }
    __syncthreads();

    // transpose out of smem: coalesced global writes along t
    float* ob = outZ + (size_t)bb * ZSTRIDE + t0;
    #pragma unroll 4
    for (int it = 0; it < 128; it++) {
        int dd = it * 2 + (tid >> 7);
        int r  = tid & 127;
        ob[(size_t)dd * T_ + r] = zsm[r * ZP + dd];
    }

    // block loss reduction -> single atomic
    #pragma unroll
    for (int s = 16; s; s >>= 1) lacc += __shfl_xor_sync(0xffffffffu, lacc, s);
    float* lsm = csm + 256;
    if ((tid & 31) == 0) lsm[tid >> 5] = lacc;
    __syncthreads();
    if (tid == 0) {
        float s = 0.0f;
        for (int k = 0; k < 8; k++) s += lsm[k];
        atomicAdd(&g_loss, s);
    }
}

// ---------------------------------------------------------------------------
// AC path: tanh quantization, codes, z_ac_q
// ---------------------------------------------------------------------------
__global__ void ac_kernel(const float* __restrict__ z, float* __restrict__ outZ,
                          float* __restrict__ outCodes, float* __restrict__ outAcq)
{
    int e = blockIdx.x * blockDim.x + threadIdx.x;
    if (e >= NAC) return;
    int b   = e / 73728;                 // 36*2048
    int rem = e - b * 73728;
    size_t off = (size_t)b * ZSTRIDE + (size_t)DSEM * T_ + rem;
    float x   = z[off];
    float zbv = tanhf(x) * 10.0f;        // HALF = 10
    float r   = rintf(zbv);              // round-half-even matches jnp.round
    float q   = zbv + (r - zbv);         // replicate STE op chain
    float cf  = rintf(q + 10.0f);
    cf = fminf(fmaxf(cf, 0.0f), 20.0f);
    outZ[off]   = q;
    outCodes[e] = cf;
    outAcq[e]   = q;
}

__global__ void fin_kernel(float* __restrict__ lossOut)
{
    float m = g_loss / 4194304.0f;       // mean over 8*256*2048
    *lossOut = m + 0.1f * m;             // codebook_loss + BETA*commitment (same mean)
}

// ---------------------------------------------------------------------------
extern "C" void kernel_launch(void* const* d_in, const int* in_sizes, int n_in,
                              void* d_out, int out_size)
{
    const float* z  = (const float*)d_in[0];
    const float* cb = (const float*)d_in[1];
    if (n_in >= 2 && in_sizes[0] == NCODE * DSEM && in_sizes[1] == B_ * DTOT * T_) {
        const float* t = z; z = cb; cb = t;   // defensive input-order swap
    }

    float* out = (float*)d_out;
    const int ZOUT = B_ * DTOT * T_;      // 4784128
    const int IDX  = NROW;                // 16384
    float *oZ, *oI, *oC, *oL, *oQ;
    if (out_size >= ZOUT + IDX + NAC + 1 + NAC) {
        oZ = out;
        oI = out + ZOUT;
        oC = oI + IDX;
        oL = oC + NAC;
        oQ = oL + 1;
    } else {
        // fallback: only z_out present; sink the rest
        float* dummy = nullptr;
        cudaGetSymbolAddress((void**)&dummy, g_dummy);
        oZ = out; oI = dummy; oC = dummy; oL = dummy; oQ = dummy;
    }

    size_t smemB = (size_t)(128 * ZP + 2 * 128 * CP) * sizeof(float);  // 150528 B
    cudaFuncSetAttribute(vq_kernel, cudaFuncAttributeMaxDynamicSharedMemorySize, (int)smemB);

    prep_kernel<<<64, 256>>>(z, cb);
    vq_kernel<<<128, 256, smemB>>>(z, cb, oZ, oI);
    ac_kernel<<<(NAC + 255) / 256, 256>>>(z, oZ, oC, oQ);
    fin_kernel<<<1, 1>>>(oL);
}

// round 8
// speedup vs baseline: 1.0026x; 1.0026x over previous
#include <cuda_runtime.h>
#include <cstdint>
#include <cstdio>

// Problem constants
#define B_     8
#define DSEM   256
#define DTOT   292
#define T_     2048
#define NROW   16384          // B*T
#define NCODE  8192
#define ZSTRIDE (DTOT * T_)   // 598016
#define NAC    (8 * 36 * 2048)  // 589824

// smem pitches
#define ZP 258                // z tile row pitch (floats), 128 rows x 256 k
#define CP 18                 // codebook tile pitch (floats), 128 codes x 16 k

// scratch (no cudaMalloc allowed)
__device__ float g_znorm[NROW];
__device__ float g_cnorm[NCODE];
__device__ float g_loss;
__device__ float g_dummy[NAC];   // sink for missing output regions

// ---------------------------------------------------------------------------
// Prep: row norms of z_sem, codebook norms, zero loss accumulator
// ---------------------------------------------------------------------------
__global__ void prep_kernel(const float* __restrict__ z, const float* __restrict__ cb)
{
    int tid = blockIdx.x * blockDim.x + threadIdx.x;
    if (tid == 0) g_loss = 0.0f;
    if (tid < NROW) {
        int b = tid >> 11, t = tid & 2047;
        const float* p = z + (size_t)b * ZSTRIDE + t;
        float s = 0.0f;
        #pragma unroll 8
        for (int d = 0; d < DSEM; d++) { float v = p[(size_t)d * T_]; s += v * v; }
        g_znorm[tid] = s;
    }
    if (tid < NCODE) {
        const float* p = cb + (size_t)tid * DSEM;
        float s = 0.0f;
        #pragma unroll 8
        for (int d = 0; d < DSEM; d++) { float v = p[d]; s += v * v; }
        g_cnorm[tid] = s;
    }
}

// packed fp32x2 FMA (SASS FFMA2) — only reachable via PTX
#define FMA2(acc, a, b) \
    asm("fma.rn.f32x2 %0, %1, %2, %0;" : "+l"(acc) : "l"(a), "l"(b))

// ---------------------------------------------------------------------------
// Fused GEMM + argmin + z_q gather + sem output + loss partial
// grid = 128 CTAs (128 rows each), 256 threads (16 tx codes x 16 ty rows)
// ---------------------------------------------------------------------------
__global__ __launch_bounds__(256, 1)
void vq_kernel(const float* __restrict__ z, const float* __restrict__ cb,
               float* __restrict__ outZ, float* __restrict__ outIdx)
{
    extern __shared__ float sm[];
    float* zsm = sm;                    // 128 * ZP floats (z tile, resident)
    float* csm = sm + 128 * ZP;         // 2 * 128 * CP floats (codebook, double buf)

    int tid = threadIdx.x;
    int tx = tid & 15, ty = tid >> 4;
    int n0 = blockIdx.x * 128;          // first row of this CTA
    int bb = n0 >> 11, t0 = n0 & 2047;
    const float* zb = z + (size_t)bb * ZSTRIDE + t0;

    // load z tile: zsm[r][k], coalesced along t (=r)
    for (int i = tid; i < 128 * DSEM; i += 256) {
        int d = i >> 7, r = i & 127;
        zsm[r * ZP + d] = zb[(size_t)d * T_ + r];
    }

    float zn[8], best[8];
    int   bidx[8];
    #pragma unroll
    for (int i = 0; i < 8; i++) {
        zn[i]   = g_znorm[n0 + ty + 16 * i];
        best[i] = 3.4e38f;
        bidx[i] = 0;
    }

    // codebook chunk loader: thread (c_ld, h_ld) loads 8 floats of one code row
    int c_ld = tid >> 1;
    int h_ld = (tid & 1) * 8;
    float4 p0, p1;
    {
        const float* g = cb + (size_t)c_ld * DSEM + h_ld;     // tile 0, chunk 0
        p0 = *(const float4*)g; p1 = *(const float4*)(g + 4);
    }
    __syncthreads();

    #pragma unroll 1
    for (int tile = 0; tile < 64; tile++) {
        int ct0 = tile * 128;
        unsigned long long acc[8][8];
        #pragma unroll
        for (int i = 0; i < 8; i++)
            #pragma unroll
            for (int j = 0; j < 8; j++) acc[i][j] = 0ULL;

        #pragma unroll 1
        for (int kc16 = 0; kc16 < 16; kc16++) {
            int bufo = (kc16 & 1) * (128 * CP);
            // store prefetched chunk (hazard covered by the mid-barrier chain)
            float* cd = csm + bufo + c_ld * CP + h_ld;
            ((float2*)cd)[0] = make_float2(p0.x, p0.y);
            ((float2*)cd)[1] = make_float2(p0.z, p0.w);
            ((float2*)cd)[2] = make_float2(p1.x, p1.y);
            ((float2*)cd)[3] = make_float2(p1.z, p1.w);
            // prefetch next chunk into registers
            {
                int nt = tile, nk = kc16 + 1;
                if (nk == 16) { nk = 0; nt = tile + 1; }
                if (nt < 64) {
                    const float* g = cb + (size_t)(nt * 128 + c_ld) * DSEM + nk * 16 + h_ld;
                    p0 = *(const float4*)g; p1 = *(const float4*)(g + 4);
                }
            }
            __syncthreads();

            int kc = kc16 * 16;
            #pragma unroll
            for (int kp = 0; kp < 8; kp++) {
                unsigned long long av[8], bv[8];
                #pragma unroll
                for (int i = 0; i < 8; i++)
                    av[i] = *(const unsigned long long*)&zsm[(ty + 16 * i) * ZP + kc + 2 * kp];
                #pragma unroll
                for (int j = 0; j < 8; j++)
                    bv[j] = *(const unsigned long long*)&csm[bufo + (tx + 16 * j) * CP + 2 * kp];
                #pragma unroll
                for (int i = 0; i < 8; i++)
                    #pragma unroll
                    for (int j = 0; j < 8; j++)
                        FMA2(acc[i][j], av[i], bv[j]);
            }
        }

        // tile epilogue: distances + running argmin (ascending order => first-min kept)
        float cn[8];
        #pragma unroll
        for (int j = 0; j < 8; j++) cn[j] = g_cnorm[ct0 + tx + 16 * j];
        #pragma unroll
        for (int i = 0; i < 8; i++) {
            #pragma unroll
            for (int j = 0; j < 8; j++) {
                unsigned long long v = acc[i][j];
                float lo = __uint_as_float((unsigned)v);
                float hi = __uint_as_float((unsigned)(v >> 32));
                float dot = lo + hi;
                float dist = (zn[i] - 2.0f * dot) + cn[j];   // replicate ref op order
                if (dist < best[i]) { best[i] = dist; bidx[i] = ct0 + tx + 16 * j; }
            }
        }
    }

    // reduce argmin across the 16 tx lanes (contiguous lanes per ty)
    #pragma unroll
    for (int i = 0; i < 8; i++) {
        #pragma unroll
        for (int s = 1; s < 16; s <<= 1) {
            float od = __shfl_xor_sync(0xffffffffu, best[i], s, 16);
            int   oi = __shfl_xor_sync(0xffffffffu, bidx[i], s, 16);
            if (od < best[i] || (od == best[i] && oi < bidx[i])) { best[i] = od; bidx[i] = oi; }
        }
    }

    int* sIdx = (int*)csm;              // reuse codebook smem
    __syncthreads();                    // all GEMM reads of csm done
    if (tx == 0) {
        #pragma unroll
        for (int i = 0; i < 8; i++) {
            int r = ty + 16 * i;
            sIdx[r] = bidx[i];
            outIdx[n0 + r] = (float)bidx[i];
        }
    }
    __syncthreads();

    // z_q gather + sem output (in-place into zsm) + loss partial
    float lacc = 0.0f;
    #pragma unroll 4
    for (int r = 0; r < 128; r++) {
        float cq = cb[(size_t)sIdx[r] * DSEM + tid];   // coalesced: all lanes same row
        float zv = zsm[r * ZP + tid];
        float df = cq - zv;
        float o  = zv + df;                            // z_sem + (z_q - z_sem), exact ref chain
        lacc = fmaf(df, df, lacc);
        zsm[r * ZP + tid] = o;
    }
    __syncthreads();

    // transpose out of smem: coalesced global writes along t
    float* ob = outZ + (size_t)bb * ZSTRIDE + t0;
    #pragma unroll 4
    for (int it = 0; it < 128; it++) {
        int dd = it * 2 + (tid >> 7);
        int r  = tid & 127;
        ob[(size_t)dd * T_ + r] = zsm[r * ZP + dd];
    }

    // block loss reduction -> single atomic
    #pragma unroll
    for (int s = 16; s; s >>= 1) lacc += __shfl_xor_sync(0xffffffffu, lacc, s);
    float* lsm = csm + 256;
    if ((tid & 31) == 0) lsm[tid >> 5] = lacc;
    __syncthreads();
    if (tid == 0) {
        float s = 0.0f;
        for (int k = 0; k < 8; k++) s += lsm[k];
        atomicAdd(&g_loss, s);
    }
}

// ---------------------------------------------------------------------------
// AC path: tanh quantization, codes, z_ac_q
// ---------------------------------------------------------------------------
__global__ void ac_kernel(const float* __restrict__ z, float* __restrict__ outZ,
                          float* __restrict__ outCodes, float* __restrict__ outAcq)
{
    int e = blockIdx.x * blockDim.x + threadIdx.x;
    if (e >= NAC) return;
    int b   = e / 73728;                 // 36*2048
    int rem = e - b * 73728;
    size_t off = (size_t)b * ZSTRIDE + (size_t)DSEM * T_ + rem;
    float x   = z[off];
    float zbv = tanhf(x) * 10.0f;        // HALF = 10
    float r   = rintf(zbv);              // round-half-even matches jnp.round
    float q   = zbv + (r - zbv);         // replicate STE op chain
    float cf  = rintf(q + 10.0f);
    cf = fminf(fmaxf(cf, 0.0f), 20.0f);
    outZ[off]   = q;
    outCodes[e] = cf;
    outAcq[e]   = q;
}

__global__ void fin_kernel(float* __restrict__ lossOut)
{
    float m = g_loss / 4194304.0f;       // mean over 8*256*2048
    *lossOut = m + 0.1f * m;             // codebook_loss + BETA*commitment (same mean)
}

// ---------------------------------------------------------------------------
extern "C" void kernel_launch(void* const* d_in, const int* in_sizes, int n_in,
                              void* d_out, int out_size)
{
    const float* z  = (const float*)d_in[0];
    const float* cb = (const float*)d_in[1];
    if (n_in >= 2 && in_sizes[0] == NCODE * DSEM && in_sizes[1] == B_ * DTOT * T_) {
        const float* t = z; z = cb; cb = t;   // defensive input-order swap
    }

    float* out = (float*)d_out;
    const int ZOUT = B_ * DTOT * T_;      // 4784128
    const int IDX  = NROW;                // 16384
    float *oZ, *oI, *oC, *oL, *oQ;
    if (out_size >= ZOUT + IDX + NAC + 1 + NAC) {
        oZ = out;
        oI = out + ZOUT;
        oC = oI + IDX;
        oL = oC + NAC;
        oQ = oL + 1;
    } else {
        // fallback: only z_out present; sink the rest
        float* dummy = nullptr;
        cudaGetSymbolAddress((void**)&dummy, g_dummy);
        oZ = out; oI = dummy; oC = dummy; oL = dummy; oQ = dummy;
    }

    size_t smemB = (size_t)(128 * ZP + 2 * 128 * CP) * sizeof(float);  // 150528 B
    cudaFuncSetAttribute(vq_kernel, cudaFuncAttributeMaxDynamicSharedMemorySize, (int)smemB);

    prep_kernel<<<64, 256>>>(z, cb);
    vq_kernel<<<128, 256, smemB>>>(z, cb, oZ, oI);
    ac_kernel<<<(NAC + 255) / 256, 256>>>(z, oZ, oC, oQ);
    fin_kernel<<<1, 1>>>(oL);
}